// round 12
// baseline (speedup 1.0000x reference)
#include <cuda_runtime.h>
#include <cstdint>

// Problem constants (fixed by the dataset)
#define Nn 50000
#define Ee 800000
#define F0 128    // F_IN
#define F1 512    // F_EMB1
#define F2 128    // F_EMB2
#define F3 1024   // F_HID
#define F4 64     // F_OUT

// ---------------------------------------------------------------------------
// Static device scratch (allocation-free rule: __device__ globals)
// ---------------------------------------------------------------------------
__device__ float g_deg[Nn];
__device__ int   g_cnt[Nn];
__device__ int   g_rowptr[Nn + 1];
__device__ int   g_fill[Nn];
__device__ int2  g_csr[Ee];                 // {src, norm as bits}
__device__ float g_aggx[(size_t)Nn * F0];   // aggregated x (layer-1, pre-transform)
__device__ float g_h[(size_t)Nn * F1];      // relu(aggx @ W1 + b1)
__device__ float g_t[(size_t)Nn * F2];      // h @ W2 (pre-aggregation)
__device__ float g_h2[(size_t)Nn * F2];     // relu(agg(t) + b2)
__device__ float g_hmid[(size_t)Nn * F3];   // relu(h2 @ W3 + b3)

// ---------------------------------------------------------------------------
// Graph preprocessing
// ---------------------------------------------------------------------------
__global__ void init_kernel() {
    int i = blockIdx.x * blockDim.x + threadIdx.x;
    if (i < Nn) { g_deg[i] = 1.0f; g_cnt[i] = 0; }   // +1 self-loop weight
}

__global__ void deg_cnt_kernel(const int* __restrict__ dst,
                               const float* __restrict__ w) {
    int e = blockIdx.x * blockDim.x + threadIdx.x;
    if (e < Ee) {
        int d = dst[e];
        atomicAdd(&g_deg[d], w[e]);
        atomicAdd(&g_cnt[d], 1);
    }
}

// Single-block exclusive scan of g_cnt -> g_rowptr / g_fill
__global__ void scan_kernel() {
    const int T = 1024;
    const int CHUNK = (Nn + T - 1) / T;   // 49
    __shared__ int sums[T];
    int t = threadIdx.x;
    int start = t * CHUNK;
    int s = 0;
    for (int i = 0; i < CHUNK; i++) {
        int idx = start + i;
        if (idx < Nn) s += g_cnt[idx];
    }
    sums[t] = s;
    __syncthreads();
    // Hillis-Steele inclusive scan
    for (int off = 1; off < T; off <<= 1) {
        int v = (t >= off) ? sums[t - off] : 0;
        __syncthreads();
        sums[t] += v;
        __syncthreads();
    }
    int run = (t == 0) ? 0 : sums[t - 1];
    for (int i = 0; i < CHUNK; i++) {
        int idx = start + i;
        if (idx < Nn) {
            g_rowptr[idx] = run;
            g_fill[idx] = run;
            run += g_cnt[idx];
        }
    }
    if (t == T - 1) g_rowptr[Nn] = run;   // == Ee
}

__global__ void place_kernel(const int* __restrict__ src,
                             const int* __restrict__ dst,
                             const float* __restrict__ w) {
    int e = blockIdx.x * blockDim.x + threadIdx.x;
    if (e < Ee) {
        int s = src[e], d = dst[e];
        float nm = rsqrtf(g_deg[s]) * w[e] * rsqrtf(g_deg[d]);
        int pos = atomicAdd(&g_fill[d], 1);
        g_csr[pos] = make_int2(s, __float_as_int(nm));
    }
}

// ---------------------------------------------------------------------------
// Aggregation: one warp per destination node, 128 features = 32 lanes x float4
// out[i] = sum_e norm_e * feat[src_e] + feat[i] / deg[i]   (+ optional bias, relu)
// ---------------------------------------------------------------------------
template <bool EPI>
__global__ __launch_bounds__(256) void agg_kernel(const float* __restrict__ feat,
                                                  const float* __restrict__ bias,
                                                  float* __restrict__ out) {
    int gw = (blockIdx.x * blockDim.x + threadIdx.x) >> 5;
    int lane = threadIdx.x & 31;
    if (gw >= Nn) return;
    const float4* f4 = (const float4*)feat;

    float inv = 1.0f / g_deg[gw];
    float4 acc = __ldg(&f4[(size_t)gw * 32 + lane]);
    acc.x *= inv; acc.y *= inv; acc.z *= inv; acc.w *= inv;

    int beg = g_rowptr[gw];
    int end = g_rowptr[gw + 1];
    for (int e = beg; e < end; e++) {
        int2 p = g_csr[e];
        float nm = __int_as_float(p.y);
        float4 v = __ldg(&f4[(size_t)p.x * 32 + lane]);
        acc.x = fmaf(nm, v.x, acc.x);
        acc.y = fmaf(nm, v.y, acc.y);
        acc.z = fmaf(nm, v.z, acc.z);
        acc.w = fmaf(nm, v.w, acc.w);
    }
    if (EPI) {
        float4 b = __ldg(&((const float4*)bias)[lane]);
        acc.x = fmaxf(acc.x + b.x, 0.0f);
        acc.y = fmaxf(acc.y + b.y, 0.0f);
        acc.z = fmaxf(acc.z + b.z, 0.0f);
        acc.w = fmaxf(acc.w + b.w, 0.0f);
    }
    ((float4*)out)[(size_t)gw * 32 + lane] = acc;
}

// ---------------------------------------------------------------------------
// SGEMM: C[M,N] = A[M,K] @ B[K,N] (+bias, relu if EPI). Row-major everything.
// BM=128, BN=64, BK=16, 256 threads, 8x4 per-thread tile.
// Requires: K % 16 == 0, N % 64 == 0 (holds for all four layers).
// ---------------------------------------------------------------------------
template <bool EPI>
__global__ __launch_bounds__(256) void sgemm_kernel(const float* __restrict__ A,
                                                    const float* __restrict__ B,
                                                    const float* __restrict__ bias,
                                                    float* __restrict__ C,
                                                    int M, int N, int K) {
    constexpr int BM = 128, BN = 64, BK = 16, TM = 8, TN = 4;
    __shared__ float As[BK][BM];
    __shared__ float Bs[BK][BN];

    int tid = threadIdx.x;
    int tx = tid & 15;   // 0..15 -> column group
    int ty = tid >> 4;   // 0..15 -> row group
    int bm = blockIdx.y * BM;
    int bn = blockIdx.x * BN;

    int arow0 = tid >> 2;        // 0..63
    int acol  = (tid & 3) * 4;   // 0,4,8,12
    int brow  = tid >> 4;        // 0..15
    int bcol  = (tid & 15) * 4;  // 0..60

    float acc[TM][TN];
#pragma unroll
    for (int i = 0; i < TM; i++)
#pragma unroll
        for (int j = 0; j < TN; j++) acc[i][j] = 0.0f;

    for (int k0 = 0; k0 < K; k0 += BK) {
        // Load A tile (128x16), transposed into As[k][m]
#pragma unroll
        for (int r = 0; r < 2; r++) {
            int row = arow0 + r * 64;
            int grow = bm + row;
            float4 v = make_float4(0.f, 0.f, 0.f, 0.f);
            if (grow < M)
                v = *(const float4*)(A + (size_t)grow * K + k0 + acol);
            As[acol + 0][row] = v.x;
            As[acol + 1][row] = v.y;
            As[acol + 2][row] = v.z;
            As[acol + 3][row] = v.w;
        }
        // Load B tile (16x64)
        {
            float4 v = *(const float4*)(B + (size_t)(k0 + brow) * N + bn + bcol);
            *(float4*)&Bs[brow][bcol] = v;
        }
        __syncthreads();

#pragma unroll
        for (int k = 0; k < BK; k++) {
            float ra[TM], rb[TN];
            float4 a0 = *(const float4*)&As[k][ty * TM];
            float4 a1 = *(const float4*)&As[k][ty * TM + 4];
            ra[0] = a0.x; ra[1] = a0.y; ra[2] = a0.z; ra[3] = a0.w;
            ra[4] = a1.x; ra[5] = a1.y; ra[6] = a1.z; ra[7] = a1.w;
            float4 b0 = *(const float4*)&Bs[k][tx * TN];
            rb[0] = b0.x; rb[1] = b0.y; rb[2] = b0.z; rb[3] = b0.w;
#pragma unroll
            for (int i = 0; i < TM; i++)
#pragma unroll
                for (int j = 0; j < TN; j++)
                    acc[i][j] = fmaf(ra[i], rb[j], acc[i][j]);
        }
        __syncthreads();
    }

    float bv[TN] = {0.f, 0.f, 0.f, 0.f};
    if (EPI) {
        float4 bb = *(const float4*)(bias + bn + tx * TN);
        bv[0] = bb.x; bv[1] = bb.y; bv[2] = bb.z; bv[3] = bb.w;
    }
#pragma unroll
    for (int i = 0; i < TM; i++) {
        int grow = bm + ty * TM + i;
        if (grow < M) {
            float4 o;
            if (EPI) {
                o.x = fmaxf(acc[i][0] + bv[0], 0.0f);
                o.y = fmaxf(acc[i][1] + bv[1], 0.0f);
                o.z = fmaxf(acc[i][2] + bv[2], 0.0f);
                o.w = fmaxf(acc[i][3] + bv[3], 0.0f);
            } else {
                o.x = acc[i][0]; o.y = acc[i][1]; o.z = acc[i][2]; o.w = acc[i][3];
            }
            *(float4*)(C + (size_t)grow * N + bn + tx * TN) = o;
        }
    }
}

// ---------------------------------------------------------------------------
// Launch
// ---------------------------------------------------------------------------
extern "C" void kernel_launch(void* const* d_in, const int* in_sizes, int n_in,
                              void* d_out, int out_size) {
    const float* x  = (const float*)d_in[0];
    const int*   ei = (const int*)d_in[1];     // [2, E]
    const float* ew = (const float*)d_in[2];
    const float* W1 = (const float*)d_in[3];
    const float* b1 = (const float*)d_in[4];
    const float* W2 = (const float*)d_in[5];
    const float* b2 = (const float*)d_in[6];
    const float* W3 = (const float*)d_in[7];
    const float* b3 = (const float*)d_in[8];
    const float* W4 = (const float*)d_in[9];
    const float* b4 = (const float*)d_in[10];
    float* out = (float*)d_out;

    const int* src = ei;
    const int* dst = ei + Ee;

    float *p_aggx, *p_h, *p_t, *p_h2, *p_hmid;
    cudaGetSymbolAddress((void**)&p_aggx, g_aggx);
    cudaGetSymbolAddress((void**)&p_h,    g_h);
    cudaGetSymbolAddress((void**)&p_t,    g_t);
    cudaGetSymbolAddress((void**)&p_h2,   g_h2);
    cudaGetSymbolAddress((void**)&p_hmid, g_hmid);

    const int TB = 256;
    int nblk = (Nn + TB - 1) / TB;
    int eblk = (Ee + TB - 1) / TB;
    int wblk = ((Nn * 32) + TB - 1) / TB;   // one warp per node

    // 1) degrees + in-degree counts
    init_kernel<<<nblk, TB>>>();
    deg_cnt_kernel<<<eblk, TB>>>(dst, ew);
    // 2) CSR build
    scan_kernel<<<1, 1024>>>();
    place_kernel<<<eblk, TB>>>(src, dst, ew);

    // 3) layer 1: aggregate x (linearity: agg(xW) = agg(x)W), then GEMM+bias+relu
    agg_kernel<false><<<wblk, TB>>>(x, nullptr, p_aggx);
    {
        dim3 grid(F1 / 64, (Nn + 127) / 128);
        sgemm_kernel<true><<<grid, 256>>>(p_aggx, W1, b1, p_h, Nn, F1, F0);
    }

    // 4) layer 2: transform first (512 -> 128), then aggregate + bias + relu
    {
        dim3 grid(F2 / 64, (Nn + 127) / 128);
        sgemm_kernel<false><<<grid, 256>>>(p_h, W2, nullptr, p_t, Nn, F2, F1);
    }
    agg_kernel<true><<<wblk, TB>>>(p_t, b2, p_h2);

    // 5) MLP
    {
        dim3 grid(F3 / 64, (Nn + 127) / 128);
        sgemm_kernel<true><<<grid, 256>>>(p_h2, W3, b3, p_hmid, Nn, F3, F2);
    }
    {
        dim3 grid(F4 / 64, (Nn + 127) / 128);
        sgemm_kernel<true><<<grid, 256>>>(p_hmid, W4, b4, out, Nn, F4, F3);
    }
}

// round 14
// speedup vs baseline: 2.0272x; 2.0272x over previous
#include <cuda_runtime.h>
#include <cstdint>

// Problem constants (fixed by the dataset)
#define Nn 50000
#define Ee 800000
#define F0 128    // F_IN
#define F1 512    // F_EMB1
#define F2 128    // F_EMB2
#define F3 1024   // F_HID
#define F4 64     // F_OUT

// ---------------------------------------------------------------------------
// Static device scratch (allocation-free rule: __device__ globals)
// ---------------------------------------------------------------------------
__device__ float g_deg[Nn];
__device__ int   g_cnt[Nn];
__device__ int   g_rowptr[Nn + 1];
__device__ int   g_fill[Nn];
__device__ int2  g_csr[Ee];                 // {src, norm as bits}
__device__ float g_aggx[(size_t)Nn * F0];   // aggregated x (layer-1, pre-transform)
__device__ float g_h[(size_t)Nn * F1];      // relu(aggx @ W1 + b1)
__device__ float g_t[(size_t)Nn * F2];      // h @ W2 (pre-aggregation)
__device__ float g_h2[(size_t)Nn * F2];     // relu(agg(t) + b2)
__device__ float g_hmid[(size_t)Nn * F3];   // relu(h2 @ W3 + b3)
// Transposed weights, K-major [N, K] (pre-rounded to tf32)
__device__ float g_w1t[(size_t)F1 * F0];
__device__ float g_w2t[(size_t)F2 * F1];
__device__ float g_w3t[(size_t)F3 * F2];
__device__ float g_w4t[(size_t)F4 * F3];

// ---------------------------------------------------------------------------
// Portable PTX helpers (sm_80+ features only — this toolchain targets
// compute_103 WITHOUT the 'a' suffix, so no tcgen05/TMA-tensor ops).
// ---------------------------------------------------------------------------
__device__ __forceinline__ uint32_t smem_u32(const void* p) {
    uint32_t a;
    asm("{ .reg .u64 t; cvta.to.shared.u64 t, %1; cvt.u32.u64 %0, t; }"
        : "=r"(a) : "l"(p));
    return a;
}

// Round-to-nearest tf32 (keeps value in fp32 encoding with low mantissa zeroed,
// so the MMA's internal truncation is lossless).
__device__ __forceinline__ float to_tf32(float x) {
    uint32_t r;
    asm("cvt.rna.tf32.f32 %0, %1;" : "=r"(r) : "f"(x));
    return __uint_as_float(r);
}

#define CP_ASYNC16(dst, src) \
    asm volatile("cp.async.cg.shared.global [%0], [%1], 16;" \
                 :: "r"(dst), "l"(src) : "memory")
#define CP_COMMIT() asm volatile("cp.async.commit_group;" ::: "memory")
#define CP_WAIT(n)  asm volatile("cp.async.wait_group %0;" :: "n"(n) : "memory")

// D += A*B  (m16n8k8, tf32 in, fp32 accumulate)
__device__ __forceinline__ void mma_tf32(float* c, const uint32_t* a,
                                         const uint32_t* b) {
    asm volatile(
        "mma.sync.aligned.m16n8k8.row.col.f32.tf32.tf32.f32 "
        "{%0,%1,%2,%3}, {%4,%5,%6,%7}, {%8,%9}, {%0,%1,%2,%3};"
        : "+f"(c[0]), "+f"(c[1]), "+f"(c[2]), "+f"(c[3])
        : "r"(a[0]), "r"(a[1]), "r"(a[2]), "r"(a[3]), "r"(b[0]), "r"(b[1]));
}

// ---------------------------------------------------------------------------
// Graph preprocessing (unchanged from R11, which passed)
// ---------------------------------------------------------------------------
__global__ void init_kernel() {
    int i = blockIdx.x * blockDim.x + threadIdx.x;
    if (i < Nn) { g_deg[i] = 1.0f; g_cnt[i] = 0; }
}

__global__ void deg_cnt_kernel(const int* __restrict__ dst,
                               const float* __restrict__ w) {
    int e = blockIdx.x * blockDim.x + threadIdx.x;
    if (e < Ee) {
        int d = dst[e];
        atomicAdd(&g_deg[d], w[e]);
        atomicAdd(&g_cnt[d], 1);
    }
}

__global__ void scan_kernel() {
    const int T = 1024;
    const int CHUNK = (Nn + T - 1) / T;
    __shared__ int sums[T];
    int t = threadIdx.x;
    int start = t * CHUNK;
    int s = 0;
    for (int i = 0; i < CHUNK; i++) {
        int idx = start + i;
        if (idx < Nn) s += g_cnt[idx];
    }
    sums[t] = s;
    __syncthreads();
    for (int off = 1; off < T; off <<= 1) {
        int v = (t >= off) ? sums[t - off] : 0;
        __syncthreads();
        sums[t] += v;
        __syncthreads();
    }
    int run = (t == 0) ? 0 : sums[t - 1];
    for (int i = 0; i < CHUNK; i++) {
        int idx = start + i;
        if (idx < Nn) {
            g_rowptr[idx] = run;
            g_fill[idx] = run;
            run += g_cnt[idx];
        }
    }
    if (t == T - 1) g_rowptr[Nn] = run;
}

__global__ void place_kernel(const int* __restrict__ src,
                             const int* __restrict__ dst,
                             const float* __restrict__ w) {
    int e = blockIdx.x * blockDim.x + threadIdx.x;
    if (e < Ee) {
        int s = src[e], d = dst[e];
        float nm = rsqrtf(g_deg[s]) * w[e] * rsqrtf(g_deg[d]);
        int pos = atomicAdd(&g_fill[d], 1);
        g_csr[pos] = make_int2(s, __float_as_int(nm));
    }
}

// Tiled transpose + tf32 pre-round: W [K,N] -> Wt [N,K]. K,N multiples of 32.
__global__ void transpose_kernel(const float* __restrict__ W,
                                 float* __restrict__ Wt, int K, int N) {
    __shared__ float t[32][33];
    int n0 = blockIdx.x * 32, k0 = blockIdx.y * 32;
    t[threadIdx.y][threadIdx.x] =
        to_tf32(W[(size_t)(k0 + threadIdx.y) * N + n0 + threadIdx.x]);
    __syncthreads();
    Wt[(size_t)(n0 + threadIdx.y) * K + k0 + threadIdx.x] = t[threadIdx.x][threadIdx.y];
}

// ---------------------------------------------------------------------------
// Aggregation: one warp per destination node (128 features = 32 lanes x float4)
// Output is pre-rounded to tf32 (it always feeds a tensor-core GEMM next).
// ---------------------------------------------------------------------------
template <bool EPI>
__global__ __launch_bounds__(256) void agg_kernel(const float* __restrict__ feat,
                                                  const float* __restrict__ bias,
                                                  float* __restrict__ out) {
    int gw = (blockIdx.x * blockDim.x + threadIdx.x) >> 5;
    int lane = threadIdx.x & 31;
    if (gw >= Nn) return;
    const float4* f4 = (const float4*)feat;

    float inv = 1.0f / g_deg[gw];
    float4 acc = __ldg(&f4[(size_t)gw * 32 + lane]);
    acc.x *= inv; acc.y *= inv; acc.z *= inv; acc.w *= inv;

    int beg = g_rowptr[gw];
    int end = g_rowptr[gw + 1];
    for (int e = beg; e < end; e++) {
        int2 p = g_csr[e];
        float nm = __int_as_float(p.y);
        float4 v = __ldg(&f4[(size_t)p.x * 32 + lane]);
        acc.x = fmaf(nm, v.x, acc.x);
        acc.y = fmaf(nm, v.y, acc.y);
        acc.z = fmaf(nm, v.z, acc.z);
        acc.w = fmaf(nm, v.w, acc.w);
    }
    if (EPI) {
        float4 b = __ldg(&((const float4*)bias)[lane]);
        acc.x = fmaxf(acc.x + b.x, 0.0f);
        acc.y = fmaxf(acc.y + b.y, 0.0f);
        acc.z = fmaxf(acc.z + b.z, 0.0f);
        acc.w = fmaxf(acc.w + b.w, 0.0f);
    }
    float4 o;
    o.x = to_tf32(acc.x); o.y = to_tf32(acc.y);
    o.z = to_tf32(acc.z); o.w = to_tf32(acc.w);
    ((float4*)out)[(size_t)gw * 32 + lane] = o;
}

// ---------------------------------------------------------------------------
// TF32 tensor-core GEMM (portable mma.sync path):
//   C[M,N] = A[M,K] @ Bt[N,K]^T  (+bias, relu if EPI; tf32-round output if CVT)
// CTA tile 128 x BN, BK=32, cp.async double-buffered, 256 threads (8 warps,
// 4x2), warp tile 32 x (BN/2). Requires K%32==0, N%BN==0, BN in {64,128}.
// SMEM rows padded to 36 floats -> all fragment LDS are bank-conflict-free.
// ---------------------------------------------------------------------------
template <int BN, bool EPI, bool CVT>
__global__ __launch_bounds__(256) void mma_gemm(const float* __restrict__ A,
                                                const float* __restrict__ Bt,
                                                const float* __restrict__ bias,
                                                float* __restrict__ C,
                                                int M, int N, int K) {
    constexpr int BM = 128, BK = 32, STR = 36;   // 36-float padded rows
    constexpr int WN = BN / 2;                    // warp n-extent
    constexpr int NT = WN / 8;                    // n-tiles per warp

    extern __shared__ float sm_f[];
    float* As0 = sm_f;                 // [2][BM][STR]
    float* Bs0 = sm_f + 2 * BM * STR;  // [2][BN][STR]
    const uint32_t smb = smem_u32(sm_f);

    const int tid = threadIdx.x;
    const int lane = tid & 31;
    const int wid = tid >> 5;
    const int bm = blockIdx.y * BM;
    const int bn = blockIdx.x * BN;

    // tile-load coordinates: each thread copies one float4 per row-pass
    const int lrow = tid >> 3;   // 0..31
    const int lq = tid & 7;      // float4 slot in a 32-float row

    const int m_base = (wid & 3) * 32;
    const int n_base = (wid >> 2) * WN;

    float acc[2][NT][4];
#pragma unroll
    for (int mi = 0; mi < 2; mi++)
#pragma unroll
        for (int ni = 0; ni < NT; ni++)
#pragma unroll
            for (int j = 0; j < 4; j++) acc[mi][ni][j] = 0.0f;

    auto prefetch = [&](int c, int s) {
        const int k0 = c * BK;
        const uint32_t abase = smb + (uint32_t)(s * BM * STR) * 4u;
#pragma unroll
        for (int p = 0; p < 4; p++) {
            int row = lrow + p * 32;
            int grow = bm + row;
            if (grow > M - 1) grow = M - 1;   // clamp: only pollutes OOB C rows
            const float* src = A + (size_t)grow * K + k0 + lq * 4;
            uint32_t dst = abase + (uint32_t)(row * STR + lq * 4) * 4u;
            CP_ASYNC16(dst, src);
        }
        const uint32_t bbase = smb + (uint32_t)((2 * BM + s * BN) * STR) * 4u;
#pragma unroll
        for (int p = 0; p < BN / 32; p++) {
            int row = lrow + p * 32;
            const float* src = Bt + (size_t)(bn + row) * K + k0 + lq * 4;
            uint32_t dst = bbase + (uint32_t)(row * STR + lq * 4) * 4u;
            CP_ASYNC16(dst, src);
        }
    };

    const int nk = K / BK;
    prefetch(0, 0);
    CP_COMMIT();

    for (int c = 0; c < nk; c++) {
        const int s = c & 1;
        if (c + 1 < nk) {
            prefetch(c + 1, s ^ 1);
            CP_COMMIT();
            CP_WAIT(1);
        } else {
            CP_WAIT(0);
        }
        __syncthreads();

        const float* Asm = As0 + s * BM * STR;
        const float* Bsm = Bs0 + s * BN * STR;
#pragma unroll
        for (int kk = 0; kk < BK / 8; kk++) {
            const int k0 = kk * 8;
            const int cidx = k0 + (lane & 3);
            uint32_t af[2][4];
#pragma unroll
            for (int mi = 0; mi < 2; mi++) {
                int r = m_base + mi * 16 + (lane >> 2);
                af[mi][0] = __float_as_uint(Asm[r * STR + cidx]);
                af[mi][1] = __float_as_uint(Asm[(r + 8) * STR + cidx]);
                af[mi][2] = __float_as_uint(Asm[r * STR + cidx + 4]);
                af[mi][3] = __float_as_uint(Asm[(r + 8) * STR + cidx + 4]);
            }
            uint32_t bf[NT][2];
#pragma unroll
            for (int ni = 0; ni < NT; ni++) {
                int r = n_base + ni * 8 + (lane >> 2);
                bf[ni][0] = __float_as_uint(Bsm[r * STR + cidx]);
                bf[ni][1] = __float_as_uint(Bsm[r * STR + cidx + 4]);
            }
#pragma unroll
            for (int mi = 0; mi < 2; mi++)
#pragma unroll
                for (int ni = 0; ni < NT; ni++)
                    mma_tf32(acc[mi][ni], af[mi], bf[ni]);
        }
        __syncthreads();
    }

    // Epilogue: c0,c1 -> (row, col..col+1); c2,c3 -> (row+8, ...)
#pragma unroll
    for (int mi = 0; mi < 2; mi++) {
        int row = bm + m_base + mi * 16 + (lane >> 2);
#pragma unroll
        for (int ni = 0; ni < NT; ni++) {
            int col = bn + n_base + ni * 8 + 2 * (lane & 3);
            float2 bb = make_float2(0.f, 0.f);
            if (EPI) bb = *(const float2*)(bias + col);

            float v0 = acc[mi][ni][0], v1 = acc[mi][ni][1];
            float v2 = acc[mi][ni][2], v3 = acc[mi][ni][3];
            if (EPI) {
                v0 = fmaxf(v0 + bb.x, 0.0f); v1 = fmaxf(v1 + bb.y, 0.0f);
                v2 = fmaxf(v2 + bb.x, 0.0f); v3 = fmaxf(v3 + bb.y, 0.0f);
            }
            if (CVT) {
                v0 = to_tf32(v0); v1 = to_tf32(v1);
                v2 = to_tf32(v2); v3 = to_tf32(v3);
            }
            if (row < M)
                *(float2*)(C + (size_t)row * N + col) = make_float2(v0, v1);
            if (row + 8 < M)
                *(float2*)(C + (size_t)(row + 8) * N + col) = make_float2(v2, v3);
        }
    }
}

// ---------------------------------------------------------------------------
// Launch
// ---------------------------------------------------------------------------
extern "C" void kernel_launch(void* const* d_in, const int* in_sizes, int n_in,
                              void* d_out, int out_size) {
    const float* x  = (const float*)d_in[0];
    const int*   ei = (const int*)d_in[1];     // [2, E]
    const float* ew = (const float*)d_in[2];
    const float* W1 = (const float*)d_in[3];
    const float* b1 = (const float*)d_in[4];
    const float* W2 = (const float*)d_in[5];
    const float* b2 = (const float*)d_in[6];
    const float* W3 = (const float*)d_in[7];
    const float* b3 = (const float*)d_in[8];
    const float* W4 = (const float*)d_in[9];
    const float* b4 = (const float*)d_in[10];
    float* out = (float*)d_out;

    const int* src = ei;
    const int* dst = ei + Ee;

    float *p_aggx, *p_h, *p_t, *p_h2, *p_hmid;
    float *p_w1t, *p_w2t, *p_w3t, *p_w4t;
    cudaGetSymbolAddress((void**)&p_aggx, g_aggx);
    cudaGetSymbolAddress((void**)&p_h,    g_h);
    cudaGetSymbolAddress((void**)&p_t,    g_t);
    cudaGetSymbolAddress((void**)&p_h2,   g_h2);
    cudaGetSymbolAddress((void**)&p_hmid, g_hmid);
    cudaGetSymbolAddress((void**)&p_w1t,  g_w1t);
    cudaGetSymbolAddress((void**)&p_w2t,  g_w2t);
    cudaGetSymbolAddress((void**)&p_w3t,  g_w3t);
    cudaGetSymbolAddress((void**)&p_w4t,  g_w4t);

    // dynamic SMEM: [2][128][36] A + [2][BN][36] B floats
    const int smem128 = (2 * 128 * 36 + 2 * 128 * 36) * 4;  // 73728
    const int smem64  = (2 * 128 * 36 + 2 * 64 * 36) * 4;   // 55296
    cudaFuncSetAttribute(mma_gemm<128, true, true>,
                         cudaFuncAttributeMaxDynamicSharedMemorySize, smem128);
    cudaFuncSetAttribute(mma_gemm<128, false, false>,
                         cudaFuncAttributeMaxDynamicSharedMemorySize, smem128);
    cudaFuncSetAttribute(mma_gemm<64, true, false>,
                         cudaFuncAttributeMaxDynamicSharedMemorySize, smem64);

    const int TB = 256;
    int nblk = (Nn + TB - 1) / TB;
    int eblk = (Ee + TB - 1) / TB;
    int wblk = ((Nn * 32) + TB - 1) / TB;
    int mtiles = (Nn + 127) / 128;   // 391

    // 0) weight transposes (K-major, tf32 pre-rounded)
    transpose_kernel<<<dim3(F1 / 32, F0 / 32), dim3(32, 32)>>>(W1, p_w1t, F0, F1);
    transpose_kernel<<<dim3(F2 / 32, F1 / 32), dim3(32, 32)>>>(W2, p_w2t, F1, F2);
    transpose_kernel<<<dim3(F3 / 32, F2 / 32), dim3(32, 32)>>>(W3, p_w3t, F2, F3);
    transpose_kernel<<<dim3(F4 / 32, F3 / 32), dim3(32, 32)>>>(W4, p_w4t, F3, F4);

    // 1) degrees + counts, 2) CSR build
    init_kernel<<<nblk, TB>>>();
    deg_cnt_kernel<<<eblk, TB>>>(dst, ew);
    scan_kernel<<<1, 1024>>>();
    place_kernel<<<eblk, TB>>>(src, dst, ew);

    // 3) layer 1: aggregate x first (linearity), then GEMM + bias + relu
    agg_kernel<false><<<wblk, TB>>>(x, nullptr, p_aggx);
    mma_gemm<128, true, true><<<dim3(F1 / 128, mtiles), 256, smem128>>>(
        p_aggx, p_w1t, b1, p_h, Nn, F1, F0);

    // 4) layer 2: transform first (512 -> 128), then aggregate + bias + relu
    mma_gemm<128, false, false><<<dim3(F2 / 128, mtiles), 256, smem128>>>(
        p_h, p_w2t, nullptr, p_t, Nn, F2, F1);
    agg_kernel<true><<<wblk, TB>>>(p_t, b2, p_h2);

    // 5) MLP
    mma_gemm<128, true, true><<<dim3(F3 / 128, mtiles), 256, smem128>>>(
        p_h2, p_w3t, b3, p_hmid, Nn, F3, F2);
    mma_gemm<64, true, false><<<dim3(F4 / 64, mtiles), 256, smem64>>>(
        p_hmid, p_w4t, b4, out, Nn, F4, F3);
}

// round 15
// speedup vs baseline: 2.7910x; 1.3768x over previous
#include <cuda_runtime.h>
#include <cuda_fp16.h>
#include <cstdint>

// Problem constants (fixed by the dataset)
#define Nn 50000
#define Ee 800000
#define F0 128    // F_IN
#define F1 512    // F_EMB1
#define F2 128    // F_EMB2
#define F3 1024   // F_HID
#define F4 64     // F_OUT

// ---------------------------------------------------------------------------
// Static device scratch (allocation-free rule: __device__ globals)
// ---------------------------------------------------------------------------
__device__ float  g_deg[Nn];
__device__ int    g_cnt[Nn];
__device__ int    g_rowptr[Nn + 1];
__device__ int    g_fill[Nn];
__device__ int2   g_csr[Ee];                  // {src, norm as bits}
__device__ __half g_aggx[(size_t)Nn * F0];    // agg(x), half (feeds GEMM1)
__device__ __half g_h[(size_t)Nn * F1];       // relu(aggx @ W1 + b1), half
__device__ __half g_t[(size_t)Nn * F2];       // h @ W2, half (feeds agg2)
__device__ __half g_h2[(size_t)Nn * F2];      // relu(agg(t) + b2), half
__device__ __half g_hmid[(size_t)Nn * F3];    // relu(h2 @ W3 + b3), half
// Transposed weights, K-major [N, K], half
__device__ __half g_w1t[(size_t)F1 * F0];
__device__ __half g_w2t[(size_t)F2 * F1];
__device__ __half g_w3t[(size_t)F3 * F2];
__device__ __half g_w4t[(size_t)F4 * F3];

// ---------------------------------------------------------------------------
// Portable PTX helpers (sm_80+ only — toolchain targets compute_103 w/o 'a')
// ---------------------------------------------------------------------------
__device__ __forceinline__ uint32_t smem_u32(const void* p) {
    uint32_t a;
    asm("{ .reg .u64 t; cvta.to.shared.u64 t, %1; cvt.u32.u64 %0, t; }"
        : "=r"(a) : "l"(p));
    return a;
}

#define CP_ASYNC16(dst, src) \
    asm volatile("cp.async.cg.shared.global [%0], [%1], 16;" \
                 :: "r"(dst), "l"(src) : "memory")
#define CP_COMMIT() asm volatile("cp.async.commit_group;" ::: "memory")
#define CP_WAIT(n)  asm volatile("cp.async.wait_group %0;" :: "n"(n) : "memory")

// D += A*B  (m16n8k16, fp16 in, fp32 accumulate)
__device__ __forceinline__ void mma_f16(float* c, const uint32_t* a,
                                        const uint32_t* b) {
    asm volatile(
        "mma.sync.aligned.m16n8k16.row.col.f32.f16.f16.f32 "
        "{%0,%1,%2,%3}, {%4,%5,%6,%7}, {%8,%9}, {%0,%1,%2,%3};"
        : "+f"(c[0]), "+f"(c[1]), "+f"(c[2]), "+f"(c[3])
        : "r"(a[0]), "r"(a[1]), "r"(a[2]), "r"(a[3]), "r"(b[0]), "r"(b[1]));
}

// ---------------------------------------------------------------------------
// Graph preprocessing (validated in R11/R13)
// ---------------------------------------------------------------------------
__global__ void init_kernel() {
    int i = blockIdx.x * blockDim.x + threadIdx.x;
    if (i < Nn) { g_deg[i] = 1.0f; g_cnt[i] = 0; }
}

__global__ void deg_cnt_kernel(const int* __restrict__ dst,
                               const float* __restrict__ w) {
    int e = blockIdx.x * blockDim.x + threadIdx.x;
    if (e < Ee) {
        int d = dst[e];
        atomicAdd(&g_deg[d], w[e]);
        atomicAdd(&g_cnt[d], 1);
    }
}

__global__ void scan_kernel() {
    const int T = 1024;
    const int CHUNK = (Nn + T - 1) / T;
    __shared__ int sums[T];
    int t = threadIdx.x;
    int start = t * CHUNK;
    int s = 0;
    for (int i = 0; i < CHUNK; i++) {
        int idx = start + i;
        if (idx < Nn) s += g_cnt[idx];
    }
    sums[t] = s;
    __syncthreads();
    for (int off = 1; off < T; off <<= 1) {
        int v = (t >= off) ? sums[t - off] : 0;
        __syncthreads();
        sums[t] += v;
        __syncthreads();
    }
    int run = (t == 0) ? 0 : sums[t - 1];
    for (int i = 0; i < CHUNK; i++) {
        int idx = start + i;
        if (idx < Nn) {
            g_rowptr[idx] = run;
            g_fill[idx] = run;
            run += g_cnt[idx];
        }
    }
    if (t == T - 1) g_rowptr[Nn] = run;
}

__global__ void place_kernel(const int* __restrict__ src,
                             const int* __restrict__ dst,
                             const float* __restrict__ w) {
    int e = blockIdx.x * blockDim.x + threadIdx.x;
    if (e < Ee) {
        int s = src[e], d = dst[e];
        float nm = rsqrtf(g_deg[s]) * w[e] * rsqrtf(g_deg[d]);
        int pos = atomicAdd(&g_fill[d], 1);
        g_csr[pos] = make_int2(s, __float_as_int(nm));
    }
}

// Tiled transpose + fp16 convert: W [K,N] fp32 -> Wt [N,K] half.
__global__ void transpose_kernel(const float* __restrict__ W,
                                 __half* __restrict__ Wt, int K, int N) {
    __shared__ float t[32][33];
    int n0 = blockIdx.x * 32, k0 = blockIdx.y * 32;
    t[threadIdx.y][threadIdx.x] = W[(size_t)(k0 + threadIdx.y) * N + n0 + threadIdx.x];
    __syncthreads();
    Wt[(size_t)(n0 + threadIdx.y) * K + k0 + threadIdx.x] =
        __float2half_rn(t[threadIdx.x][threadIdx.y]);
}

// ---------------------------------------------------------------------------
// Aggregation: one warp per destination node, 128 features = 32 lanes x 4.
// fp32 accumulation, half output (always feeds a GEMM).
// FP32IN: layer-1 reads the fp32 input x; layer-2 reads the half buffer t.
// ---------------------------------------------------------------------------
template <bool EPI, bool FP32IN>
__global__ __launch_bounds__(256) void agg_kernel(const void* __restrict__ featv,
                                                  const float* __restrict__ bias,
                                                  __half* __restrict__ out) {
    int gw = (blockIdx.x * blockDim.x + threadIdx.x) >> 5;
    int lane = threadIdx.x & 31;
    if (gw >= Nn) return;

    const float4* ff = (const float4*)featv;   // fp32 path
    const uint2*  fh = (const uint2*)featv;    // half path (4 halves)

    float a0, a1, a2, a3;
    if (FP32IN) {
        float4 v = __ldg(&ff[(size_t)gw * 32 + lane]);
        a0 = v.x; a1 = v.y; a2 = v.z; a3 = v.w;
    } else {
        uint2 v = __ldg(&fh[(size_t)gw * 32 + lane]);
        float2 p0 = __half22float2(*(__half2*)&v.x);
        float2 p1 = __half22float2(*(__half2*)&v.y);
        a0 = p0.x; a1 = p0.y; a2 = p1.x; a3 = p1.y;
    }
    float inv = 1.0f / g_deg[gw];
    a0 *= inv; a1 *= inv; a2 *= inv; a3 *= inv;

    int beg = g_rowptr[gw];
    int end = g_rowptr[gw + 1];
    for (int e = beg; e < end; e++) {
        int2 p = g_csr[e];
        float nm = __int_as_float(p.y);
        float v0, v1, v2, v3;
        if (FP32IN) {
            float4 v = __ldg(&ff[(size_t)p.x * 32 + lane]);
            v0 = v.x; v1 = v.y; v2 = v.z; v3 = v.w;
        } else {
            uint2 v = __ldg(&fh[(size_t)p.x * 32 + lane]);
            float2 p0 = __half22float2(*(__half2*)&v.x);
            float2 p1 = __half22float2(*(__half2*)&v.y);
            v0 = p0.x; v1 = p0.y; v2 = p1.x; v3 = p1.y;
        }
        a0 = fmaf(nm, v0, a0);
        a1 = fmaf(nm, v1, a1);
        a2 = fmaf(nm, v2, a2);
        a3 = fmaf(nm, v3, a3);
    }
    if (EPI) {
        float4 b = __ldg(&((const float4*)bias)[lane]);
        a0 = fmaxf(a0 + b.x, 0.0f);
        a1 = fmaxf(a1 + b.y, 0.0f);
        a2 = fmaxf(a2 + b.z, 0.0f);
        a3 = fmaxf(a3 + b.w, 0.0f);
    }
    uint2 o;
    __half2 h0 = __float22half2_rn(make_float2(a0, a1));
    __half2 h1 = __float22half2_rn(make_float2(a2, a3));
    o.x = *(uint32_t*)&h0;
    o.y = *(uint32_t*)&h1;
    ((uint2*)out)[(size_t)gw * 32 + lane] = o;
}

// ---------------------------------------------------------------------------
// FP16 tensor-core GEMM (portable mma.sync m16n8k16):
//   C[M,N] = A[M,K] @ Bt[N,K]^T  (+bias, relu if EPI)
// A, Bt are half; accumulate fp32; output half (or fp32 if OUTF32).
// CTA tile 128 x BN, BK=32 halves, cp.async double-buffered, 256 threads
// (8 warps, 4x2), warp tile 32 x (BN/2). K%32==0, N%BN==0, BN in {64,128}.
// SMEM rows padded to 40 halves (80B) -> fragment LDS conflict-free.
// ---------------------------------------------------------------------------
template <int BN, bool EPI, bool OUTF32>
__global__ __launch_bounds__(256) void mma_gemm(const __half* __restrict__ A,
                                                const __half* __restrict__ Bt,
                                                const float* __restrict__ bias,
                                                void* __restrict__ Cv,
                                                int M, int N, int K) {
    constexpr int BM = 128, BK = 32, STR = 40;   // halves per padded row
    constexpr int WN = BN / 2;
    constexpr int NT = WN / 8;

    extern __shared__ __half sm_h[];
    __half* As0 = sm_h;                  // [2][BM][STR]
    __half* Bs0 = sm_h + 2 * BM * STR;   // [2][BN][STR]
    const uint32_t smb = smem_u32(sm_h);

    const int tid = threadIdx.x;
    const int lane = tid & 31;
    const int wid = tid >> 5;
    const int bm = blockIdx.y * BM;
    const int bn = blockIdx.x * BN;

    // tile-load coords: row of 32 halves = 64B = 4 x cp.async(16B)
    const int lrow = tid >> 2;   // 0..63
    const int lq = tid & 3;      // 16B slot

    const int m_base = (wid & 3) * 32;
    const int n_base = (wid >> 2) * WN;

    float acc[2][NT][4];
#pragma unroll
    for (int mi = 0; mi < 2; mi++)
#pragma unroll
        for (int ni = 0; ni < NT; ni++)
#pragma unroll
            for (int j = 0; j < 4; j++) acc[mi][ni][j] = 0.0f;

    auto prefetch = [&](int c, int s) {
        const int k0 = c * BK;
        const uint32_t abase = smb + (uint32_t)(s * BM * STR) * 2u;
#pragma unroll
        for (int p = 0; p < 2; p++) {            // A: 128 rows, 64 per pass
            int row = lrow + p * 64;
            int grow = bm + row;
            if (grow > M - 1) grow = M - 1;      // clamp: only pollutes OOB rows
            const __half* src = A + (size_t)grow * K + k0 + lq * 8;
            uint32_t dst = abase + (uint32_t)(row * STR) * 2u + (uint32_t)lq * 16u;
            CP_ASYNC16(dst, src);
        }
        const uint32_t bbase = smb + (uint32_t)((2 * BM + s * BN) * STR) * 2u;
#pragma unroll
        for (int p = 0; p < BN / 64; p++) {      // B: BN rows
            int row = lrow + p * 64;
            const __half* src = Bt + (size_t)(bn + row) * K + k0 + lq * 8;
            uint32_t dst = bbase + (uint32_t)(row * STR) * 2u + (uint32_t)lq * 16u;
            CP_ASYNC16(dst, src);
        }
    };

    const int nk = K / BK;
    prefetch(0, 0);
    CP_COMMIT();

    for (int c = 0; c < nk; c++) {
        const int s = c & 1;
        if (c + 1 < nk) {
            prefetch(c + 1, s ^ 1);
            CP_COMMIT();
            CP_WAIT(1);
        } else {
            CP_WAIT(0);
        }
        __syncthreads();

        const __half* Asm = As0 + s * BM * STR;
        const __half* Bsm = Bs0 + s * BN * STR;
#pragma unroll
        for (int kk = 0; kk < BK / 16; kk++) {   // two k16 steps per chunk
            const int c0 = kk * 16 + 2 * (lane & 3);
            uint32_t af[2][4];
#pragma unroll
            for (int mi = 0; mi < 2; mi++) {
                int r = m_base + mi * 16 + (lane >> 2);
                af[mi][0] = *(const uint32_t*)&Asm[r * STR + c0];
                af[mi][1] = *(const uint32_t*)&Asm[(r + 8) * STR + c0];
                af[mi][2] = *(const uint32_t*)&Asm[r * STR + c0 + 8];
                af[mi][3] = *(const uint32_t*)&Asm[(r + 8) * STR + c0 + 8];
            }
            uint32_t bf[NT][2];
#pragma unroll
            for (int ni = 0; ni < NT; ni++) {
                int n = n_base + ni * 8 + (lane >> 2);
                bf[ni][0] = *(const uint32_t*)&Bsm[n * STR + c0];
                bf[ni][1] = *(const uint32_t*)&Bsm[n * STR + c0 + 8];
            }
#pragma unroll
            for (int mi = 0; mi < 2; mi++)
#pragma unroll
                for (int ni = 0; ni < NT; ni++)
                    mma_f16(acc[mi][ni], af[mi], bf[ni]);
        }
        __syncthreads();
    }

    // Epilogue: c0,c1 -> (row, col..col+1); c2,c3 -> (row+8, ...)
    float* Cf = (float*)Cv;
    __half* Ch = (__half*)Cv;
#pragma unroll
    for (int mi = 0; mi < 2; mi++) {
        int row = bm + m_base + mi * 16 + (lane >> 2);
#pragma unroll
        for (int ni = 0; ni < NT; ni++) {
            int col = bn + n_base + ni * 8 + 2 * (lane & 3);
            float2 bb = make_float2(0.f, 0.f);
            if (EPI) bb = *(const float2*)(bias + col);

            float v0 = acc[mi][ni][0], v1 = acc[mi][ni][1];
            float v2 = acc[mi][ni][2], v3 = acc[mi][ni][3];
            if (EPI) {
                v0 = fmaxf(v0 + bb.x, 0.0f); v1 = fmaxf(v1 + bb.y, 0.0f);
                v2 = fmaxf(v2 + bb.x, 0.0f); v3 = fmaxf(v3 + bb.y, 0.0f);
            }
            if (OUTF32) {
                if (row < M)
                    *(float2*)(Cf + (size_t)row * N + col) = make_float2(v0, v1);
                if (row + 8 < M)
                    *(float2*)(Cf + (size_t)(row + 8) * N + col) = make_float2(v2, v3);
            } else {
                if (row < M) {
                    __half2 h = __float22half2_rn(make_float2(v0, v1));
                    *(uint32_t*)(Ch + (size_t)row * N + col) = *(uint32_t*)&h;
                }
                if (row + 8 < M) {
                    __half2 h = __float22half2_rn(make_float2(v2, v3));
                    *(uint32_t*)(Ch + (size_t)(row + 8) * N + col) = *(uint32_t*)&h;
                }
            }
        }
    }
}

// ---------------------------------------------------------------------------
// Launch
// ---------------------------------------------------------------------------
extern "C" void kernel_launch(void* const* d_in, const int* in_sizes, int n_in,
                              void* d_out, int out_size) {
    const float* x  = (const float*)d_in[0];
    const int*   ei = (const int*)d_in[1];     // [2, E]
    const float* ew = (const float*)d_in[2];
    const float* W1 = (const float*)d_in[3];
    const float* b1 = (const float*)d_in[4];
    const float* W2 = (const float*)d_in[5];
    const float* b2 = (const float*)d_in[6];
    const float* W3 = (const float*)d_in[7];
    const float* b3 = (const float*)d_in[8];
    const float* W4 = (const float*)d_in[9];
    const float* b4 = (const float*)d_in[10];
    float* out = (float*)d_out;

    const int* src = ei;
    const int* dst = ei + Ee;

    __half *p_aggx, *p_h, *p_t, *p_h2, *p_hmid;
    __half *p_w1t, *p_w2t, *p_w3t, *p_w4t;
    cudaGetSymbolAddress((void**)&p_aggx, g_aggx);
    cudaGetSymbolAddress((void**)&p_h,    g_h);
    cudaGetSymbolAddress((void**)&p_t,    g_t);
    cudaGetSymbolAddress((void**)&p_h2,   g_h2);
    cudaGetSymbolAddress((void**)&p_hmid, g_hmid);
    cudaGetSymbolAddress((void**)&p_w1t,  g_w1t);
    cudaGetSymbolAddress((void**)&p_w2t,  g_w2t);
    cudaGetSymbolAddress((void**)&p_w3t,  g_w3t);
    cudaGetSymbolAddress((void**)&p_w4t,  g_w4t);

    // dynamic SMEM: ([2][128] + [2][BN]) x 40 halves
    const int smem128 = (2 * 128 * 40 + 2 * 128 * 40) * 2;  // 40960
    const int smem64  = (2 * 128 * 40 + 2 * 64 * 40) * 2;   // 30720
    cudaFuncSetAttribute(mma_gemm<128, true, false>,
                         cudaFuncAttributeMaxDynamicSharedMemorySize, smem128);
    cudaFuncSetAttribute(mma_gemm<128, false, false>,
                         cudaFuncAttributeMaxDynamicSharedMemorySize, smem128);
    cudaFuncSetAttribute(mma_gemm<64, true, true>,
                         cudaFuncAttributeMaxDynamicSharedMemorySize, smem64);

    const int TB = 256;
    int nblk = (Nn + TB - 1) / TB;
    int eblk = (Ee + TB - 1) / TB;
    int wblk = ((Nn * 32) + TB - 1) / TB;
    int mtiles = (Nn + 127) / 128;   // 391

    // 0) weight transposes (K-major, fp16)
    transpose_kernel<<<dim3(F1 / 32, F0 / 32), dim3(32, 32)>>>(W1, p_w1t, F0, F1);
    transpose_kernel<<<dim3(F2 / 32, F1 / 32), dim3(32, 32)>>>(W2, p_w2t, F1, F2);
    transpose_kernel<<<dim3(F3 / 32, F2 / 32), dim3(32, 32)>>>(W3, p_w3t, F2, F3);
    transpose_kernel<<<dim3(F4 / 32, F3 / 32), dim3(32, 32)>>>(W4, p_w4t, F3, F4);

    // 1) degrees + counts, 2) CSR build
    init_kernel<<<nblk, TB>>>();
    deg_cnt_kernel<<<eblk, TB>>>(dst, ew);
    scan_kernel<<<1, 1024>>>();
    place_kernel<<<eblk, TB>>>(src, dst, ew);

    // 3) layer 1: aggregate x first (linearity), then GEMM + bias + relu
    agg_kernel<false, true><<<wblk, TB>>>(x, nullptr, p_aggx);
    mma_gemm<128, true, false><<<dim3(F1 / 128, mtiles), 256, smem128>>>(
        p_aggx, p_w1t, b1, p_h, Nn, F1, F0);

    // 4) layer 2: transform first (512 -> 128), then aggregate + bias + relu
    mma_gemm<128, false, false><<<dim3(F2 / 128, mtiles), 256, smem128>>>(
        p_h, p_w2t, nullptr, p_t, Nn, F2, F1);
    agg_kernel<true, false><<<wblk, TB>>>(p_t, b2, p_h2);

    // 5) MLP
    mma_gemm<128, true, false><<<dim3(F3 / 128, mtiles), 256, smem128>>>(
        p_h2, p_w3t, b3, p_hmid, Nn, F3, F2);
    mma_gemm<64, true, true><<<dim3(F4 / 64, mtiles), 256, smem64>>>(
        p_hmid, p_w4t, b4, out, Nn, F4, F3);
}

// round 16
// speedup vs baseline: 2.8017x; 1.0038x over previous
#include <cuda_runtime.h>
#include <cuda_fp16.h>
#include <cstdint>

// Problem constants (fixed by the dataset)
#define Nn 50000
#define Ee 800000
#define F0 128    // F_IN
#define F1 512    // F_EMB1
#define F2 128    // F_EMB2
#define F3 1024   // F_HID
#define F4 64     // F_OUT

// ---------------------------------------------------------------------------
// Static device scratch (allocation-free rule: __device__ globals)
// ---------------------------------------------------------------------------
__device__ float  g_deg[Nn];
__device__ int    g_cnt[Nn];
__device__ int    g_rowptr[Nn + 1];
__device__ int    g_fill[Nn];
__device__ int2   g_csr[Ee];                  // {src, norm as bits}
__device__ __half g_aggx[(size_t)Nn * F0];    // agg(x), half (feeds GEMM1)
__device__ __half g_h[(size_t)Nn * F1];       // relu(aggx @ W1 + b1), half
__device__ __half g_t[(size_t)Nn * F2];       // h @ W2, half (feeds agg2)
__device__ __half g_h2[(size_t)Nn * F2];      // relu(agg(t) + b2), half
__device__ __half g_hmid[(size_t)Nn * F3];    // relu(h2 @ W3 + b3), half
// Transposed weights, K-major [N, K], half
__device__ __half g_w1t[(size_t)F1 * F0];
__device__ __half g_w2t[(size_t)F2 * F1];
__device__ __half g_w3t[(size_t)F3 * F2];
__device__ __half g_w4t[(size_t)F4 * F3];

// ---------------------------------------------------------------------------
// Portable PTX helpers (sm_80+ only — toolchain targets compute_103 w/o 'a')
// ---------------------------------------------------------------------------
__device__ __forceinline__ uint32_t smem_u32(const void* p) {
    uint32_t a;
    asm("{ .reg .u64 t; cvta.to.shared.u64 t, %1; cvt.u32.u64 %0, t; }"
        : "=r"(a) : "l"(p));
    return a;
}

#define CP_ASYNC16(dst, src) \
    asm volatile("cp.async.cg.shared.global [%0], [%1], 16;" \
                 :: "r"(dst), "l"(src) : "memory")
#define CP_COMMIT() asm volatile("cp.async.commit_group;" ::: "memory")
#define CP_WAIT(n)  asm volatile("cp.async.wait_group %0;" :: "n"(n) : "memory")

// D += A*B  (m16n8k16, fp16 in, fp32 accumulate)
__device__ __forceinline__ void mma_f16(float* c, const uint32_t* a,
                                        const uint32_t* b) {
    asm volatile(
        "mma.sync.aligned.m16n8k16.row.col.f32.f16.f16.f32 "
        "{%0,%1,%2,%3}, {%4,%5,%6,%7}, {%8,%9}, {%0,%1,%2,%3};"
        : "+f"(c[0]), "+f"(c[1]), "+f"(c[2]), "+f"(c[3])
        : "r"(a[0]), "r"(a[1]), "r"(a[2]), "r"(a[3]), "r"(b[0]), "r"(b[1]));
}

// ---------------------------------------------------------------------------
// Graph preprocessing (validated in R11/R13)
// ---------------------------------------------------------------------------
__global__ void init_kernel() {
    int i = blockIdx.x * blockDim.x + threadIdx.x;
    if (i < Nn) { g_deg[i] = 1.0f; g_cnt[i] = 0; }
}

__global__ void deg_cnt_kernel(const int* __restrict__ dst,
                               const float* __restrict__ w) {
    int e = blockIdx.x * blockDim.x + threadIdx.x;
    if (e < Ee) {
        int d = dst[e];
        atomicAdd(&g_deg[d], w[e]);
        atomicAdd(&g_cnt[d], 1);
    }
}

__global__ void scan_kernel() {
    const int T = 1024;
    const int CHUNK = (Nn + T - 1) / T;
    __shared__ int sums[T];
    int t = threadIdx.x;
    int start = t * CHUNK;
    int s = 0;
    for (int i = 0; i < CHUNK; i++) {
        int idx = start + i;
        if (idx < Nn) s += g_cnt[idx];
    }
    sums[t] = s;
    __syncthreads();
    for (int off = 1; off < T; off <<= 1) {
        int v = (t >= off) ? sums[t - off] : 0;
        __syncthreads();
        sums[t] += v;
        __syncthreads();
    }
    int run = (t == 0) ? 0 : sums[t - 1];
    for (int i = 0; i < CHUNK; i++) {
        int idx = start + i;
        if (idx < Nn) {
            g_rowptr[idx] = run;
            g_fill[idx] = run;
            run += g_cnt[idx];
        }
    }
    if (t == T - 1) g_rowptr[Nn] = run;
}

__global__ void place_kernel(const int* __restrict__ src,
                             const int* __restrict__ dst,
                             const float* __restrict__ w) {
    int e = blockIdx.x * blockDim.x + threadIdx.x;
    if (e < Ee) {
        int s = src[e], d = dst[e];
        float nm = rsqrtf(g_deg[s]) * w[e] * rsqrtf(g_deg[d]);
        int pos = atomicAdd(&g_fill[d], 1);
        g_csr[pos] = make_int2(s, __float_as_int(nm));
    }
}

// Tiled transpose + fp16 convert: W [K,N] fp32 -> Wt [N,K] half.
__global__ void transpose_kernel(const float* __restrict__ W,
                                 __half* __restrict__ Wt, int K, int N) {
    __shared__ float t[32][33];
    int n0 = blockIdx.x * 32, k0 = blockIdx.y * 32;
    t[threadIdx.y][threadIdx.x] = W[(size_t)(k0 + threadIdx.y) * N + n0 + threadIdx.x];
    __syncthreads();
    Wt[(size_t)(n0 + threadIdx.y) * K + k0 + threadIdx.x] =
        __float2half_rn(t[threadIdx.x][threadIdx.y]);
}

// ---------------------------------------------------------------------------
// Aggregation: one warp per destination node, 128 features = 32 lanes x 4.
// fp32 accumulation, half output (always feeds a GEMM).
// FP32IN: layer-1 reads the fp32 input x; layer-2 reads the half buffer t.
// ---------------------------------------------------------------------------
template <bool EPI, bool FP32IN>
__global__ __launch_bounds__(256) void agg_kernel(const void* __restrict__ featv,
                                                  const float* __restrict__ bias,
                                                  __half* __restrict__ out) {
    int gw = (blockIdx.x * blockDim.x + threadIdx.x) >> 5;
    int lane = threadIdx.x & 31;
    if (gw >= Nn) return;

    const float4* ff = (const float4*)featv;   // fp32 path
    const uint2*  fh = (const uint2*)featv;    // half path (4 halves)

    float a0, a1, a2, a3;
    if (FP32IN) {
        float4 v = __ldg(&ff[(size_t)gw * 32 + lane]);
        a0 = v.x; a1 = v.y; a2 = v.z; a3 = v.w;
    } else {
        uint2 v = __ldg(&fh[(size_t)gw * 32 + lane]);
        float2 p0 = __half22float2(*(__half2*)&v.x);
        float2 p1 = __half22float2(*(__half2*)&v.y);
        a0 = p0.x; a1 = p0.y; a2 = p1.x; a3 = p1.y;
    }
    float inv = 1.0f / g_deg[gw];
    a0 *= inv; a1 *= inv; a2 *= inv; a3 *= inv;

    int beg = g_rowptr[gw];
    int end = g_rowptr[gw + 1];
    for (int e = beg; e < end; e++) {
        int2 p = g_csr[e];
        float nm = __int_as_float(p.y);
        float v0, v1, v2, v3;
        if (FP32IN) {
            float4 v = __ldg(&ff[(size_t)p.x * 32 + lane]);
            v0 = v.x; v1 = v.y; v2 = v.z; v3 = v.w;
        } else {
            uint2 v = __ldg(&fh[(size_t)p.x * 32 + lane]);
            float2 p0 = __half22float2(*(__half2*)&v.x);
            float2 p1 = __half22float2(*(__half2*)&v.y);
            v0 = p0.x; v1 = p0.y; v2 = p1.x; v3 = p1.y;
        }
        a0 = fmaf(nm, v0, a0);
        a1 = fmaf(nm, v1, a1);
        a2 = fmaf(nm, v2, a2);
        a3 = fmaf(nm, v3, a3);
    }
    if (EPI) {
        float4 b = __ldg(&((const float4*)bias)[lane]);
        a0 = fmaxf(a0 + b.x, 0.0f);
        a1 = fmaxf(a1 + b.y, 0.0f);
        a2 = fmaxf(a2 + b.z, 0.0f);
        a3 = fmaxf(a3 + b.w, 0.0f);
    }
    uint2 o;
    __half2 h0 = __float22half2_rn(make_float2(a0, a1));
    __half2 h1 = __float22half2_rn(make_float2(a2, a3));
    o.x = *(uint32_t*)&h0;
    o.y = *(uint32_t*)&h1;
    ((uint2*)out)[(size_t)gw * 32 + lane] = o;
}

// ---------------------------------------------------------------------------
// FP16 tensor-core GEMM (portable mma.sync m16n8k16):
//   C[M,N] = A[M,K] @ Bt[N,K]^T  (+bias, relu if EPI)
// A, Bt are half; accumulate fp32; output half (or fp32 if OUTF32).
// CTA tile 128 x BN, BK=32 halves, cp.async double-buffered, 256 threads
// (8 warps, 4x2), warp tile 32 x (BN/2). K%32==0, N%BN==0, BN in {64,128}.
// SMEM rows padded to 40 halves (80B) -> fragment LDS conflict-free.
// ---------------------------------------------------------------------------
template <int BN, bool EPI, bool OUTF32>
__global__ __launch_bounds__(256) void mma_gemm(const __half* __restrict__ A,
                                                const __half* __restrict__ Bt,
                                                const float* __restrict__ bias,
                                                void* __restrict__ Cv,
                                                int M, int N, int K) {
    constexpr int BM = 128, BK = 32, STR = 40;   // halves per padded row
    constexpr int WN = BN / 2;
    constexpr int NT = WN / 8;

    extern __shared__ __half sm_h[];
    __half* As0 = sm_h;                  // [2][BM][STR]
    __half* Bs0 = sm_h + 2 * BM * STR;   // [2][BN][STR]
    const uint32_t smb = smem_u32(sm_h);

    const int tid = threadIdx.x;
    const int lane = tid & 31;
    const int wid = tid >> 5;
    const int bm = blockIdx.y * BM;
    const int bn = blockIdx.x * BN;

    // tile-load coords: row of 32 halves = 64B = 4 x cp.async(16B)
    const int lrow = tid >> 2;   // 0..63
    const int lq = tid & 3;      // 16B slot

    const int m_base = (wid & 3) * 32;
    const int n_base = (wid >> 2) * WN;

    float acc[2][NT][4];
#pragma unroll
    for (int mi = 0; mi < 2; mi++)
#pragma unroll
        for (int ni = 0; ni < NT; ni++)
#pragma unroll
            for (int j = 0; j < 4; j++) acc[mi][ni][j] = 0.0f;

    auto prefetch = [&](int c, int s) {
        const int k0 = c * BK;
        const uint32_t abase = smb + (uint32_t)(s * BM * STR) * 2u;
#pragma unroll
        for (int p = 0; p < 2; p++) {            // A: 128 rows, 64 per pass
            int row = lrow + p * 64;
            int grow = bm + row;
            if (grow > M - 1) grow = M - 1;      // clamp: only pollutes OOB rows
            const __half* src = A + (size_t)grow * K + k0 + lq * 8;
            uint32_t dst = abase + (uint32_t)(row * STR) * 2u + (uint32_t)lq * 16u;
            CP_ASYNC16(dst, src);
        }
        const uint32_t bbase = smb + (uint32_t)((2 * BM + s * BN) * STR) * 2u;
#pragma unroll
        for (int p = 0; p < BN / 64; p++) {      // B: BN rows
            int row = lrow + p * 64;
            const __half* src = Bt + (size_t)(bn + row) * K + k0 + lq * 8;
            uint32_t dst = bbase + (uint32_t)(row * STR) * 2u + (uint32_t)lq * 16u;
            CP_ASYNC16(dst, src);
        }
    };

    const int nk = K / BK;
    prefetch(0, 0);
    CP_COMMIT();

    for (int c = 0; c < nk; c++) {
        const int s = c & 1;
        if (c + 1 < nk) {
            prefetch(c + 1, s ^ 1);
            CP_COMMIT();
            CP_WAIT(1);
        } else {
            CP_WAIT(0);
        }
        __syncthreads();

        const __half* Asm = As0 + s * BM * STR;
        const __half* Bsm = Bs0 + s * BN * STR;
#pragma unroll
        for (int kk = 0; kk < BK / 16; kk++) {   // two k16 steps per chunk
            const int c0 = kk * 16 + 2 * (lane & 3);
            uint32_t af[2][4];
#pragma unroll
            for (int mi = 0; mi < 2; mi++) {
                int r = m_base + mi * 16 + (lane >> 2);
                af[mi][0] = *(const uint32_t*)&Asm[r * STR + c0];
                af[mi][1] = *(const uint32_t*)&Asm[(r + 8) * STR + c0];
                af[mi][2] = *(const uint32_t*)&Asm[r * STR + c0 + 8];
                af[mi][3] = *(const uint32_t*)&Asm[(r + 8) * STR + c0 + 8];
            }
            uint32_t bf[NT][2];
#pragma unroll
            for (int ni = 0; ni < NT; ni++) {
                int n = n_base + ni * 8 + (lane >> 2);
                bf[ni][0] = *(const uint32_t*)&Bsm[n * STR + c0];
                bf[ni][1] = *(const uint32_t*)&Bsm[n * STR + c0 + 8];
            }
#pragma unroll
            for (int mi = 0; mi < 2; mi++)
#pragma unroll
                for (int ni = 0; ni < NT; ni++)
                    mma_f16(acc[mi][ni], af[mi], bf[ni]);
        }
        __syncthreads();
    }

    // Epilogue: c0,c1 -> (row, col..col+1); c2,c3 -> (row+8, ...)
    float* Cf = (float*)Cv;
    __half* Ch = (__half*)Cv;
#pragma unroll
    for (int mi = 0; mi < 2; mi++) {
        int row = bm + m_base + mi * 16 + (lane >> 2);
#pragma unroll
        for (int ni = 0; ni < NT; ni++) {
            int col = bn + n_base + ni * 8 + 2 * (lane & 3);
            float2 bb = make_float2(0.f, 0.f);
            if (EPI) bb = *(const float2*)(bias + col);

            float v0 = acc[mi][ni][0], v1 = acc[mi][ni][1];
            float v2 = acc[mi][ni][2], v3 = acc[mi][ni][3];
            if (EPI) {
                v0 = fmaxf(v0 + bb.x, 0.0f); v1 = fmaxf(v1 + bb.y, 0.0f);
                v2 = fmaxf(v2 + bb.x, 0.0f); v3 = fmaxf(v3 + bb.y, 0.0f);
            }
            if (OUTF32) {
                if (row < M)
                    *(float2*)(Cf + (size_t)row * N + col) = make_float2(v0, v1);
                if (row + 8 < M)
                    *(float2*)(Cf + (size_t)(row + 8) * N + col) = make_float2(v2, v3);
            } else {
                if (row < M) {
                    __half2 h = __float22half2_rn(make_float2(v0, v1));
                    *(uint32_t*)(Ch + (size_t)row * N + col) = *(uint32_t*)&h;
                }
                if (row + 8 < M) {
                    __half2 h = __float22half2_rn(make_float2(v2, v3));
                    *(uint32_t*)(Ch + (size_t)(row + 8) * N + col) = *(uint32_t*)&h;
                }
            }
        }
    }
}

// ---------------------------------------------------------------------------
// Launch
// ---------------------------------------------------------------------------
extern "C" void kernel_launch(void* const* d_in, const int* in_sizes, int n_in,
                              void* d_out, int out_size) {
    const float* x  = (const float*)d_in[0];
    const int*   ei = (const int*)d_in[1];     // [2, E]
    const float* ew = (const float*)d_in[2];
    const float* W1 = (const float*)d_in[3];
    const float* b1 = (const float*)d_in[4];
    const float* W2 = (const float*)d_in[5];
    const float* b2 = (const float*)d_in[6];
    const float* W3 = (const float*)d_in[7];
    const float* b3 = (const float*)d_in[8];
    const float* W4 = (const float*)d_in[9];
    const float* b4 = (const float*)d_in[10];
    float* out = (float*)d_out;

    const int* src = ei;
    const int* dst = ei + Ee;

    __half *p_aggx, *p_h, *p_t, *p_h2, *p_hmid;
    __half *p_w1t, *p_w2t, *p_w3t, *p_w4t;
    cudaGetSymbolAddress((void**)&p_aggx, g_aggx);
    cudaGetSymbolAddress((void**)&p_h,    g_h);
    cudaGetSymbolAddress((void**)&p_t,    g_t);
    cudaGetSymbolAddress((void**)&p_h2,   g_h2);
    cudaGetSymbolAddress((void**)&p_hmid, g_hmid);
    cudaGetSymbolAddress((void**)&p_w1t,  g_w1t);
    cudaGetSymbolAddress((void**)&p_w2t,  g_w2t);
    cudaGetSymbolAddress((void**)&p_w3t,  g_w3t);
    cudaGetSymbolAddress((void**)&p_w4t,  g_w4t);

    // dynamic SMEM: ([2][128] + [2][BN]) x 40 halves
    const int smem128 = (2 * 128 * 40 + 2 * 128 * 40) * 2;  // 40960
    const int smem64  = (2 * 128 * 40 + 2 * 64 * 40) * 2;   // 30720
    cudaFuncSetAttribute(mma_gemm<128, true, false>,
                         cudaFuncAttributeMaxDynamicSharedMemorySize, smem128);
    cudaFuncSetAttribute(mma_gemm<128, false, false>,
                         cudaFuncAttributeMaxDynamicSharedMemorySize, smem128);
    cudaFuncSetAttribute(mma_gemm<64, true, true>,
                         cudaFuncAttributeMaxDynamicSharedMemorySize, smem64);

    const int TB = 256;
    int nblk = (Nn + TB - 1) / TB;
    int eblk = (Ee + TB - 1) / TB;
    int wblk = ((Nn * 32) + TB - 1) / TB;
    int mtiles = (Nn + 127) / 128;   // 391

    // 0) weight transposes (K-major, fp16)
    transpose_kernel<<<dim3(F1 / 32, F0 / 32), dim3(32, 32)>>>(W1, p_w1t, F0, F1);
    transpose_kernel<<<dim3(F2 / 32, F1 / 32), dim3(32, 32)>>>(W2, p_w2t, F1, F2);
    transpose_kernel<<<dim3(F3 / 32, F2 / 32), dim3(32, 32)>>>(W3, p_w3t, F2, F3);
    transpose_kernel<<<dim3(F4 / 32, F3 / 32), dim3(32, 32)>>>(W4, p_w4t, F3, F4);

    // 1) degrees + counts, 2) CSR build
    init_kernel<<<nblk, TB>>>();
    deg_cnt_kernel<<<eblk, TB>>>(dst, ew);
    scan_kernel<<<1, 1024>>>();
    place_kernel<<<eblk, TB>>>(src, dst, ew);

    // 3) layer 1: aggregate x first (linearity), then GEMM + bias + relu
    agg_kernel<false, true><<<wblk, TB>>>(x, nullptr, p_aggx);
    mma_gemm<128, true, false><<<dim3(F1 / 128, mtiles), 256, smem128>>>(
        p_aggx, p_w1t, b1, p_h, Nn, F1, F0);

    // 4) layer 2: transform first (512 -> 128), then aggregate + bias + relu
    mma_gemm<128, false, false><<<dim3(F2 / 128, mtiles), 256, smem128>>>(
        p_h, p_w2t, nullptr, p_t, Nn, F2, F1);
    agg_kernel<true, false><<<wblk, TB>>>(p_t, b2, p_h2);

    // 5) MLP
    mma_gemm<128, true, false><<<dim3(F3 / 128, mtiles), 256, smem128>>>(
        p_h2, p_w3t, b3, p_hmid, Nn, F3, F2);
    mma_gemm<64, true, true><<<dim3(F4 / 64, mtiles), 256, smem64>>>(
        p_hmid, p_w4t, b4, out, Nn, F4, F3);
}